// round 15
// baseline (speedup 1.0000x reference)
#include <cuda_runtime.h>
#include <cstdint>

#define N_NODES 10000
#define N_EDGES 160000
#define D 512
#define F_IN 6
#define DEPTH 10

#define NB_BUILD 160
#define NB_CHAIN 64
#define NB_CSR   96
#define NB_PASS  80

// ---------------- scratch (device globals; no allocation allowed) ----------
__device__ int    g_deg[N_NODES];
__device__ int    g_rowptr[N_NODES + 1];
__device__ int    g_cursor[N_NODES];
__device__ int    g_csr[N_EDGES];
__device__ float  g_agg6[N_NODES * F_IN];
__device__ __align__(16) float g_uc[12][D];   // u_11..u_1 chain (u_l = g_uc[l])
__device__ float  g_c[12];                    // c_l = b_l . u_{l+1}
__device__ float2 g_zd[2][N_NODES];           // (z_k, d_k) ping-pong
// grid-barrier counters (self-cleaning across calls; BSS-zero on first call)
__device__ unsigned g_ctrA, g_ctrB, g_ctrC;

// ---------------- software grid barrier -------------------------------------
__device__ __forceinline__ void gbar(unsigned* c, unsigned target) {
    __syncthreads();
    if (threadIdx.x == 0) {
        __threadfence();
        atomicAdd(c, 1u);
        while (*((volatile unsigned*)c) < target) { }
        __threadfence();
    }
    __syncthreads();
}

// ---------------- kernel 1: CSR build + agg_in  ||  weight chain ------------
__global__ __launch_bounds__(256) void build_k(
    const float* __restrict__ feat, const float* __restrict__ Ws,
    const float* __restrict__ bs, const float* __restrict__ W_out,
    const int* __restrict__ src, const int* __restrict__ dst) {
    int tid = threadIdx.x;
    int blk = blockIdx.x;
    __shared__ float sred[8];
    __shared__ int   wsum[8];

    if (blk == 0 && tid == 0) g_ctrC = 0;    // prep passes_k's counter

    if (blk < NB_CHAIN) {
        // ---- group B: collapsed weight chain (64 blocks, warp per row) ----
        int gi = blk * 256 + tid;
        if (gi < D) g_uc[11][gi] = W_out[gi];
        if (blk == 0 && tid == 0) g_c[0] = 0.f;
        gbar(&g_ctrB, NB_CHAIN * 1);

        int warp = tid >> 5, lane = tid & 31;
        int row = blk * 8 + warp;             // 512 rows total
        for (int s = 0; s < DEPTH; s++) {
            int l = DEPTH - s;                // 10 down to 1
            const float4* Wr = (const float4*)(Ws + (size_t)(l - 1) * D * D
                                                  + (size_t)row * D);
            const float4* uv = (const float4*)g_uc[l + 1];
            float acc = 0.f;
            #pragma unroll
            for (int j = lane; j < D / 4; j += 32) {
                float4 a = Wr[j], b = uv[j];
                acc += a.x * b.x + a.y * b.y + a.z * b.z + a.w * b.w;
            }
            #pragma unroll
            for (int o = 16; o; o >>= 1)
                acc += __shfl_down_sync(0xffffffffu, acc, o);
            if (lane == 0) g_uc[l][row] = acc;
            gbar(&g_ctrB, NB_CHAIN * (s + 2));
        }
        // c_l = b_l . u_{l+1}: block j computes c_{j+1} (u values L1-fresh)
        if (blk < 10) {
            const float* bv = bs + (size_t)blk * D;
            const float* uv = g_uc[blk + 2];
            float s = 0.f;
            for (int i = tid; i < D; i += 256) s += bv[i] * uv[i];
            #pragma unroll
            for (int o = 16; o; o >>= 1)
                s += __shfl_down_sync(0xffffffffu, s, o);
            if ((tid & 31) == 0) sred[tid >> 5] = s;
            __syncthreads();
            if (tid == 0) {
                float t = 0.f;
                #pragma unroll
                for (int w = 0; w < 8; w++) t += sred[w];
                g_c[blk + 1] = t;
            }
        }
    } else {
        // ---- group A: CSR build + feature aggregation (96 blocks) ----
        int ga = blk - NB_CHAIN;
        int gt = ga * 256 + tid;              // 0..24575
        if (gt < N_NODES) g_deg[gt] = 0;
        gbar(&g_ctrA, NB_CSR * 1);

        for (int e = gt; e < N_EDGES; e += NB_CSR * 256)
            atomicAdd(&g_deg[dst[e]], 1);
        gbar(&g_ctrA, NB_CSR * 2);

        if (ga == 0) {
            // scan: 256 threads x 40 elems (250 active), shuffle block-scan
            int base = tid * 40;
            int lsum = 0;
            if (base < N_NODES)
                for (int q = 0; q < 40; q++)
                    lsum += __ldcg(&g_deg[base + q]);   // L2 (atomics wrote L2)
            unsigned lane = tid & 31, w = tid >> 5;
            int inc = lsum;
            #pragma unroll
            for (int o = 1; o < 32; o <<= 1) {
                int t = __shfl_up_sync(0xffffffffu, inc, o);
                if (lane >= o) inc += t;
            }
            if (lane == 31) wsum[w] = inc;
            __syncthreads();
            if (w == 0 && lane < 8) {
                int v = wsum[lane];
                #pragma unroll
                for (int o = 1; o < 8; o <<= 1) {
                    int t = __shfl_up_sync(0xffu, v, o);
                    if (lane >= o) v += t;
                }
                wsum[lane] = v;
            }
            __syncthreads();
            int run = inc - lsum + (w ? wsum[w - 1] : 0);
            if (base < N_NODES) {
                for (int q = 0; q < 40; q++) {
                    int dv = __ldcg(&g_deg[base + q]);
                    g_rowptr[base + q] = run;
                    g_cursor[base + q] = run;
                    run += dv;
                }
            }
            if (tid == 0) g_rowptr[N_NODES] = wsum[7];
        }
        gbar(&g_ctrA, NB_CSR * 3);

        for (int e = gt; e < N_EDGES; e += NB_CSR * 256) {
            int p = atomicAdd(&g_cursor[dst[e]], 1);
            g_csr[p] = src[e];
        }
        gbar(&g_ctrA, NB_CSR * 4);

        if (gt < N_NODES) {
            float a0 = 0, a1 = 0, a2 = 0, a3 = 0, a4 = 0, a5 = 0;
            int b = g_rowptr[gt], e = g_rowptr[gt + 1];
            for (int i = b; i < e; i++) {
                const float* f = feat + (size_t)g_csr[i] * F_IN;
                a0 += f[0]; a1 += f[1]; a2 += f[2];
                a3 += f[3]; a4 += f[4]; a5 += f[5];
            }
            float* o = g_agg6 + (size_t)gt * F_IN;
            o[0] = a0; o[1] = a1; o[2] = a2; o[3] = a3; o[4] = a4; o[5] = a5;
        }
    }
}

// ---- kernel 2: z0 = relu(agg6 @ W_in + b_in) . u_1  (2 threads per node) ---
__global__ __launch_bounds__(128) void z0_k(const float* __restrict__ W_in,
                                            const float* __restrict__ b_in) {
    int g = blockIdx.x * 128 + threadIdx.x;
    int n = g >> 1, half = g & 1;
    bool act = (n < N_NODES);
    float z = 0.f;
    if (act) {
        const float* a = g_agg6 + (size_t)n * F_IN;
        float a0 = a[0], a1 = a[1], a2 = a[2], a3 = a[3], a4 = a[4], a5 = a[5];
        const float4* W0 = (const float4*)W_in;     // [f][c] as f*128 + j
        const float4* B4 = (const float4*)b_in;
        const float4* U4 = (const float4*)g_uc[1];
        int j0 = half * 64;
        #pragma unroll 4
        for (int j = j0; j < j0 + 64; j++) {
            float4 w0 = W0[j],        w1 = W0[128 + j], w2 = W0[256 + j];
            float4 w3 = W0[384 + j],  w4 = W0[512 + j], w5 = W0[640 + j];
            float4 bb = B4[j], uu = U4[j];
            float h;
            h = bb.x + a0*w0.x + a1*w1.x + a2*w2.x + a3*w3.x + a4*w4.x + a5*w5.x;
            z += fmaxf(h, 0.f) * uu.x;
            h = bb.y + a0*w0.y + a1*w1.y + a2*w2.y + a3*w3.y + a4*w4.y + a5*w5.y;
            z += fmaxf(h, 0.f) * uu.y;
            h = bb.z + a0*w0.z + a1*w1.z + a2*w2.z + a3*w3.z + a4*w4.z + a5*w5.z;
            z += fmaxf(h, 0.f) * uu.z;
            h = bb.w + a0*w0.w + a1*w1.w + a2*w2.w + a3*w3.w + a4*w4.w + a5*w5.w;
            z += fmaxf(h, 0.f) * uu.w;
        }
    }
    z += __shfl_xor_sync(0xffffffffu, z, 1);
    if (act && half == 0) g_zd[0][n] = make_float2(z, 1.0f);
}

// ---- kernel 3: all 10 aggregation passes + final assembly (persistent) -----
__global__ __launch_bounds__(128) void passes_k(const float* __restrict__ b_out,
                                                float* __restrict__ out) {
    int n = blockIdx.x * 128 + threadIdx.x;      // 10240 threads
    bool act = (n < N_NODES);
    int b = 0, e = 0;
    float acc = 0.f, sz = 0.f;
    if (act) {
        b = g_rowptr[n];
        e = g_rowptr[n + 1];
        acc = g_c[10];                           // c_10 * d_0 (d_0 = 1)
    }
    for (int p = 1; p <= DEPTH; p++) {
        const float2* srcb = g_zd[(p - 1) & 1];
        float2*       dstb = g_zd[p & 1];
        if (act) {
            sz = 0.f;
            float sd = 0.f;
            for (int i = b; i < e; i++) {
                float2 v = __ldcg(&srcb[g_csr[i]]);   // L2 (cross-SM ping-pong)
                sz += v.x; sd += v.y;
            }
            if (p < DEPTH) {
                dstb[n] = make_float2(sz, sd);
                acc += g_c[10 - p] * sd;
            }
        }
        if (p < DEPTH) gbar(&g_ctrC, (unsigned)(NB_PASS * p));
    }
    if (act) out[n] = sz + acc + b_out[0];
    if (blockIdx.x == 0 && threadIdx.x == 0) { g_ctrA = 0; g_ctrB = 0; }
}

// ---------------- launch ----------------------------------------------------
extern "C" void kernel_launch(void* const* d_in, const int* in_sizes, int n_in,
                              void* d_out, int out_size) {
    const float* features = (const float*)d_in[0];
    const float* W_in     = (const float*)d_in[1];
    const float* b_in     = (const float*)d_in[2];
    const float* Ws       = (const float*)d_in[3];
    const float* bs       = (const float*)d_in[4];
    const float* W_out    = (const float*)d_in[5];
    const float* b_out    = (const float*)d_in[6];
    const int*   src      = (const int*)d_in[7];
    const int*   dst      = (const int*)d_in[8];
    float* out = (float*)d_out;

    build_k<<<NB_BUILD, 256>>>(features, Ws, bs, W_out, src, dst);
    z0_k<<<157, 128>>>(W_in, b_in);
    passes_k<<<NB_PASS, 128>>>(b_out, out);
}

// round 16
// speedup vs baseline: 1.1275x; 1.1275x over previous
#include <cuda_runtime.h>
#include <cstdint>

#define N_NODES 10000
#define N_EDGES 160000
#define D 512
#define F_IN 6
#define DEPTH 10

#define NB_CHAIN 16
#define NB_CSR   96
#define NB_BUILD (NB_CHAIN + NB_CSR)

// ---------------- scratch (device globals; no allocation allowed) ----------
__device__ int    g_deg[N_NODES];
__device__ int    g_rowptr[N_NODES + 1];
__device__ int    g_cursor[N_NODES];
__device__ int    g_csr[N_EDGES];
__device__ float  g_agg6[N_NODES * F_IN];
__device__ __align__(16) float g_uc[12][D];   // u_l = g_uc[l]; u_11 = W_out
__device__ float  g_c[12];                    // c_l = b_l . u_{l+1}; g_c[0]=0
__device__ float2 g_zd[2][N_NODES];           // (z_k, d_k) ping-pong
__device__ float  g_acc[N_NODES];             // running bias-term accumulator
__device__ unsigned g_ctrA, g_ctrB;           // barrier counters (self-clean)

// ---------------- software grid barrier -------------------------------------
__device__ __forceinline__ void gbar(unsigned* c, unsigned target) {
    __syncthreads();
    if (threadIdx.x == 0) {
        __threadfence();
        atomicAdd(c, 1u);
        while (*((volatile unsigned*)c) < target) { }
        __threadfence();
    }
    __syncthreads();
}

// ------ kernel 1: [blocks 0..15] weight chain || [16..111] CSR + agg_in -----
__global__ __launch_bounds__(256) void build_k(
    const float* __restrict__ feat, const float* __restrict__ Ws,
    const float* __restrict__ bs, const float* __restrict__ W_out,
    const int* __restrict__ src, const int* __restrict__ dst) {
    int tid = threadIdx.x;
    int blk = blockIdx.x;
    __shared__ float sred[8];
    __shared__ int   wsum[8];

    if (blk < NB_CHAIN) {
        // ---- collapsed weight chain: 16 blocks, 4 rows per warp ----
        int gi = blk * 256 + tid;
        if (gi < D) g_uc[11][gi] = W_out[gi];
        if (blk == 0 && tid == 0) g_c[0] = 0.f;
        gbar(&g_ctrB, NB_CHAIN * 1);

        int warp = tid >> 5, lane = tid & 31;
        int r0 = blk * 32 + warp * 4;                 // rows r0..r0+3
        for (int s = 0; s < DEPTH; s++) {
            int l = DEPTH - s;                        // 10 down to 1
            const float4* W4 = (const float4*)(Ws + (size_t)(l - 1) * D * D);
            const float4* uv = (const float4*)g_uc[l + 1];
            float a0 = 0.f, a1 = 0.f, a2 = 0.f, a3 = 0.f;
            #pragma unroll
            for (int k = 0; k < 4; k++) {
                int j = lane + k * 32;
                float4 u  = uv[j];
                float4 w0 = W4[(size_t)(r0 + 0) * (D / 4) + j];
                float4 w1 = W4[(size_t)(r0 + 1) * (D / 4) + j];
                float4 w2 = W4[(size_t)(r0 + 2) * (D / 4) + j];
                float4 w3 = W4[(size_t)(r0 + 3) * (D / 4) + j];
                a0 += w0.x*u.x + w0.y*u.y + w0.z*u.z + w0.w*u.w;
                a1 += w1.x*u.x + w1.y*u.y + w1.z*u.z + w1.w*u.w;
                a2 += w2.x*u.x + w2.y*u.y + w2.z*u.z + w2.w*u.w;
                a3 += w3.x*u.x + w3.y*u.y + w3.z*u.z + w3.w*u.w;
            }
            #pragma unroll
            for (int o = 16; o; o >>= 1) {
                a0 += __shfl_down_sync(0xffffffffu, a0, o);
                a1 += __shfl_down_sync(0xffffffffu, a1, o);
                a2 += __shfl_down_sync(0xffffffffu, a2, o);
                a3 += __shfl_down_sync(0xffffffffu, a3, o);
            }
            if (lane == 0) {
                g_uc[l][r0 + 0] = a0;
                g_uc[l][r0 + 1] = a1;
                g_uc[l][r0 + 2] = a2;
                g_uc[l][r0 + 3] = a3;
            }
            gbar(&g_ctrB, NB_CHAIN * (s + 2));
        }
        // c_{blk+1} = b_{blk+1} . u_{blk+2}  (blocks 0..9)
        if (blk < 10) {
            const float* bv = bs + (size_t)blk * D;
            const float* uv = g_uc[blk + 2];
            float s = 0.f;
            for (int i = tid; i < D; i += 256) s += bv[i] * uv[i];
            #pragma unroll
            for (int o = 16; o; o >>= 1)
                s += __shfl_down_sync(0xffffffffu, s, o);
            if ((tid & 31) == 0) sred[tid >> 5] = s;
            __syncthreads();
            if (tid == 0) {
                float t = 0.f;
                #pragma unroll
                for (int w = 0; w < 8; w++) t += sred[w];
                g_c[blk + 1] = t;
            }
        }
    } else {
        // ---- CSR build + feature aggregation (96 blocks) ----
        int ga = blk - NB_CHAIN;
        int gt = ga * 256 + tid;                      // 0..24575
        if (gt < N_NODES) g_deg[gt] = 0;
        gbar(&g_ctrA, NB_CSR * 1);

        for (int e = gt; e < N_EDGES; e += NB_CSR * 256)
            atomicAdd(&g_deg[dst[e]], 1);
        gbar(&g_ctrA, NB_CSR * 2);

        if (ga == 0) {
            // fast scan: 256 threads x 40 elems, shuffle block-scan
            int base = tid * 40;
            int lsum = 0;
            if (base < N_NODES)
                for (int q = 0; q < 40; q++)
                    lsum += __ldcg(&g_deg[base + q]);
            unsigned lane = tid & 31, w = tid >> 5;
            int inc = lsum;
            #pragma unroll
            for (int o = 1; o < 32; o <<= 1) {
                int t = __shfl_up_sync(0xffffffffu, inc, o);
                if (lane >= o) inc += t;
            }
            if (lane == 31) wsum[w] = inc;
            __syncthreads();
            if (w == 0 && lane < 8) {
                int v = wsum[lane];
                #pragma unroll
                for (int o = 1; o < 8; o <<= 1) {
                    int t = __shfl_up_sync(0xffu, v, o);
                    if (lane >= o) v += t;
                }
                wsum[lane] = v;
            }
            __syncthreads();
            int run = inc - lsum + (w ? wsum[w - 1] : 0);
            if (base < N_NODES) {
                for (int q = 0; q < 40; q++) {
                    int dv = __ldcg(&g_deg[base + q]);
                    g_rowptr[base + q] = run;
                    g_cursor[base + q] = run;
                    run += dv;
                }
            }
            if (tid == 0) g_rowptr[N_NODES] = wsum[7];
        }
        gbar(&g_ctrA, NB_CSR * 3);

        for (int e = gt; e < N_EDGES; e += NB_CSR * 256) {
            int p = atomicAdd(&g_cursor[dst[e]], 1);
            g_csr[p] = src[e];
        }
        gbar(&g_ctrA, NB_CSR * 4);

        if (gt < N_NODES) {
            float a0 = 0, a1 = 0, a2 = 0, a3 = 0, a4 = 0, a5 = 0;
            int b = g_rowptr[gt], e = g_rowptr[gt + 1];
            for (int i = b; i < e; i++) {
                const float* f = feat + (size_t)g_csr[i] * F_IN;
                a0 += f[0]; a1 += f[1]; a2 += f[2];
                a3 += f[3]; a4 += f[4]; a5 += f[5];
            }
            float* o = g_agg6 + (size_t)gt * F_IN;
            o[0] = a0; o[1] = a1; o[2] = a2; o[3] = a3; o[4] = a4; o[5] = a5;
        }
    }
}

// ---- kernel 2: z0 = relu(agg6 @ W_in + b_in) . u_1 ; acc = c_10 ------------
__global__ __launch_bounds__(128) void z0_k(const float* __restrict__ W_in,
                                            const float* __restrict__ b_in) {
    int g = blockIdx.x * 128 + threadIdx.x;
    int n = g >> 1, half = g & 1;
    bool act = (n < N_NODES);
    float z = 0.f;
    if (act) {
        const float* a = g_agg6 + (size_t)n * F_IN;
        float a0 = a[0], a1 = a[1], a2 = a[2], a3 = a[3], a4 = a[4], a5 = a[5];
        const float4* W0 = (const float4*)W_in;     // [f][c]: f*128 + j
        const float4* B4 = (const float4*)b_in;
        const float4* U4 = (const float4*)g_uc[1];
        int j0 = half * 64;
        #pragma unroll 4
        for (int j = j0; j < j0 + 64; j++) {
            float4 w0 = W0[j],       w1 = W0[128 + j], w2 = W0[256 + j];
            float4 w3 = W0[384 + j], w4 = W0[512 + j], w5 = W0[640 + j];
            float4 bb = B4[j], uu = U4[j];
            float h;
            h = bb.x + a0*w0.x + a1*w1.x + a2*w2.x + a3*w3.x + a4*w4.x + a5*w5.x;
            z += fmaxf(h, 0.f) * uu.x;
            h = bb.y + a0*w0.y + a1*w1.y + a2*w2.y + a3*w3.y + a4*w4.y + a5*w5.y;
            z += fmaxf(h, 0.f) * uu.y;
            h = bb.z + a0*w0.z + a1*w1.z + a2*w2.z + a3*w3.z + a4*w4.z + a5*w5.z;
            z += fmaxf(h, 0.f) * uu.z;
            h = bb.w + a0*w0.w + a1*w1.w + a2*w2.w + a3*w3.w + a4*w4.w + a5*w5.w;
            z += fmaxf(h, 0.f) * uu.w;
        }
    }
    z += __shfl_xor_sync(0xffffffffu, z, 1);
    if (act && half == 0) {
        g_zd[0][n] = make_float2(z, 1.0f);
        g_acc[n] = g_c[10];                        // c_10 * d_0
    }
}

// ---- kernel 3 (x10): one aggregation pass; p==10 fuses final assembly ------
__global__ __launch_bounds__(256) void pass_k(int p, const float* __restrict__ b_out,
                                              float* __restrict__ out) {
    int n = blockIdx.x * 256 + threadIdx.x;
    if (p == DEPTH && n == 0) { g_ctrA = 0; g_ctrB = 0; }  // self-clean barriers
    if (n >= N_NODES) return;
    const float2* srcb = g_zd[(p - 1) & 1];
    int b = g_rowptr[n], e = g_rowptr[n + 1];
    float sz = 0.f, sd = 0.f;
    for (int i = b; i < e; i++) {
        float2 v = srcb[g_csr[i]];
        sz += v.x; sd += v.y;
    }
    if (p < DEPTH) {
        g_zd[p & 1][n] = make_float2(sz, sd);
        g_acc[n] += g_c[10 - p] * sd;
    } else {
        out[n] = sz + g_acc[n] + b_out[0];
    }
}

// ---------------- launch ----------------------------------------------------
extern "C" void kernel_launch(void* const* d_in, const int* in_sizes, int n_in,
                              void* d_out, int out_size) {
    const float* features = (const float*)d_in[0];
    const float* W_in     = (const float*)d_in[1];
    const float* b_in     = (const float*)d_in[2];
    const float* Ws       = (const float*)d_in[3];
    const float* bs       = (const float*)d_in[4];
    const float* W_out    = (const float*)d_in[5];
    const float* b_out    = (const float*)d_in[6];
    const int*   src      = (const int*)d_in[7];
    const int*   dst      = (const int*)d_in[8];
    float* out = (float*)d_out;

    build_k<<<NB_BUILD, 256>>>(features, Ws, bs, W_out, src, dst);
    z0_k<<<157, 128>>>(W_in, b_in);
    for (int p = 1; p <= DEPTH; p++)
        pass_k<<<(N_NODES + 255) / 256, 256>>>(p, b_out, out);
}

// round 17
// speedup vs baseline: 1.2560x; 1.1140x over previous
#include <cuda_runtime.h>
#include <cstdint>

#define N_NODES 10000
#define N_EDGES 160000
#define D 512
#define F_IN 6
#define DEPTH 10

#define NB_CHAIN 16
#define NB_CSR   96
#define NB_BUILD (NB_CHAIN + NB_CSR)
#define NB_PASS  ((8 * N_NODES + 255) / 256)   // 313

// ---------------- scratch (device globals; no allocation allowed) ----------
__device__ int    g_deg[N_NODES];
__device__ int    g_rowptr[N_NODES + 1];
__device__ int    g_cursor[N_NODES];
__device__ int    g_csr[N_EDGES];
__device__ float  g_agg6[N_NODES * F_IN];
__device__ __align__(16) float g_uc[12][D];   // u_l = g_uc[l]; u_11 = W_out
__device__ float  g_c[12];                    // c_l = b_l . u_{l+1}; g_c[0]=0
__device__ float2 g_zd[2][N_NODES];           // (z_k, d_k) ping-pong
__device__ float  g_acc[N_NODES];             // running bias-term accumulator
__device__ unsigned g_ctrA, g_ctrB;           // barrier counters (self-clean)

// ---------------- software grid barrier -------------------------------------
__device__ __forceinline__ void gbar(unsigned* c, unsigned target) {
    __syncthreads();
    if (threadIdx.x == 0) {
        __threadfence();
        atomicAdd(c, 1u);
        while (*((volatile unsigned*)c) < target) { }
        __threadfence();
    }
    __syncthreads();
}

// ------ kernel 1: [blocks 0..15] weight chain || [16..111] CSR + agg_in -----
__global__ __launch_bounds__(256) void build_k(
    const float* __restrict__ feat, const float* __restrict__ Ws,
    const float* __restrict__ bs, const float* __restrict__ W_out,
    const int* __restrict__ src, const int* __restrict__ dst) {
    int tid = threadIdx.x;
    int blk = blockIdx.x;
    __shared__ float sred[8];
    __shared__ int   wsum[8];

    if (blk < NB_CHAIN) {
        // ---- collapsed weight chain: 16 blocks, 4 rows per warp ----
        int gi = blk * 256 + tid;
        if (gi < D) g_uc[11][gi] = W_out[gi];
        if (blk == 0 && tid == 0) g_c[0] = 0.f;
        gbar(&g_ctrB, NB_CHAIN * 1);

        int warp = tid >> 5, lane = tid & 31;
        int r0 = blk * 32 + warp * 4;                 // rows r0..r0+3
        for (int s = 0; s < DEPTH; s++) {
            int l = DEPTH - s;                        // 10 down to 1
            const float4* W4 = (const float4*)(Ws + (size_t)(l - 1) * D * D);
            const float4* uv = (const float4*)g_uc[l + 1];
            float a0 = 0.f, a1 = 0.f, a2 = 0.f, a3 = 0.f;
            #pragma unroll
            for (int k = 0; k < 4; k++) {
                int j = lane + k * 32;
                float4 u  = uv[j];
                float4 w0 = W4[(size_t)(r0 + 0) * (D / 4) + j];
                float4 w1 = W4[(size_t)(r0 + 1) * (D / 4) + j];
                float4 w2 = W4[(size_t)(r0 + 2) * (D / 4) + j];
                float4 w3 = W4[(size_t)(r0 + 3) * (D / 4) + j];
                a0 += w0.x*u.x + w0.y*u.y + w0.z*u.z + w0.w*u.w;
                a1 += w1.x*u.x + w1.y*u.y + w1.z*u.z + w1.w*u.w;
                a2 += w2.x*u.x + w2.y*u.y + w2.z*u.z + w2.w*u.w;
                a3 += w3.x*u.x + w3.y*u.y + w3.z*u.z + w3.w*u.w;
            }
            #pragma unroll
            for (int o = 16; o; o >>= 1) {
                a0 += __shfl_down_sync(0xffffffffu, a0, o);
                a1 += __shfl_down_sync(0xffffffffu, a1, o);
                a2 += __shfl_down_sync(0xffffffffu, a2, o);
                a3 += __shfl_down_sync(0xffffffffu, a3, o);
            }
            if (lane == 0) {
                g_uc[l][r0 + 0] = a0;
                g_uc[l][r0 + 1] = a1;
                g_uc[l][r0 + 2] = a2;
                g_uc[l][r0 + 3] = a3;
            }
            gbar(&g_ctrB, NB_CHAIN * (s + 2));
        }
        // c_{blk+1} = b_{blk+1} . u_{blk+2}  (blocks 0..9)
        if (blk < 10) {
            const float* bv = bs + (size_t)blk * D;
            const float* uv = g_uc[blk + 2];
            float s = 0.f;
            for (int i = tid; i < D; i += 256) s += bv[i] * uv[i];
            #pragma unroll
            for (int o = 16; o; o >>= 1)
                s += __shfl_down_sync(0xffffffffu, s, o);
            if ((tid & 31) == 0) sred[tid >> 5] = s;
            __syncthreads();
            if (tid == 0) {
                float t = 0.f;
                #pragma unroll
                for (int w = 0; w < 8; w++) t += sred[w];
                g_c[blk + 1] = t;
            }
        }
    } else {
        // ---- CSR build + feature aggregation (96 blocks) ----
        int ga = blk - NB_CHAIN;
        int gt = ga * 256 + tid;                      // 0..24575
        if (gt < N_NODES) g_deg[gt] = 0;
        gbar(&g_ctrA, NB_CSR * 1);

        for (int e = gt; e < N_EDGES; e += NB_CSR * 256)
            atomicAdd(&g_deg[dst[e]], 1);
        gbar(&g_ctrA, NB_CSR * 2);

        if (ga == 0) {
            // fast scan: 256 threads x 40 elems, shuffle block-scan
            int base = tid * 40;
            int lsum = 0;
            if (base < N_NODES)
                for (int q = 0; q < 40; q++)
                    lsum += __ldcg(&g_deg[base + q]);
            unsigned lane = tid & 31, w = tid >> 5;
            int inc = lsum;
            #pragma unroll
            for (int o = 1; o < 32; o <<= 1) {
                int t = __shfl_up_sync(0xffffffffu, inc, o);
                if (lane >= o) inc += t;
            }
            if (lane == 31) wsum[w] = inc;
            __syncthreads();
            if (w == 0 && lane < 8) {
                int v = wsum[lane];
                #pragma unroll
                for (int o = 1; o < 8; o <<= 1) {
                    int t = __shfl_up_sync(0xffu, v, o);
                    if (lane >= o) v += t;
                }
                wsum[lane] = v;
            }
            __syncthreads();
            int run = inc - lsum + (w ? wsum[w - 1] : 0);
            if (base < N_NODES) {
                for (int q = 0; q < 40; q++) {
                    int dv = __ldcg(&g_deg[base + q]);
                    g_rowptr[base + q] = run;
                    g_cursor[base + q] = run;
                    run += dv;
                }
            }
            if (tid == 0) g_rowptr[N_NODES] = wsum[7];
        }
        gbar(&g_ctrA, NB_CSR * 3);

        for (int e = gt; e < N_EDGES; e += NB_CSR * 256) {
            int p = atomicAdd(&g_cursor[dst[e]], 1);
            g_csr[p] = src[e];
        }
        gbar(&g_ctrA, NB_CSR * 4);

        // feature aggregation: 2 threads per node (pair within warp)
        {
            int n2 = gt >> 1, hf = gt & 1;
            float a0 = 0, a1 = 0, a2 = 0, a3 = 0, a4 = 0, a5 = 0;
            if (n2 < N_NODES) {
                int b = g_rowptr[n2], e = g_rowptr[n2 + 1];
                for (int i = b + hf; i < e; i += 2) {
                    const float* f = feat + (size_t)g_csr[i] * F_IN;
                    a0 += f[0]; a1 += f[1]; a2 += f[2];
                    a3 += f[3]; a4 += f[4]; a5 += f[5];
                }
            }
            a0 += __shfl_xor_sync(0xffffffffu, a0, 1);
            a1 += __shfl_xor_sync(0xffffffffu, a1, 1);
            a2 += __shfl_xor_sync(0xffffffffu, a2, 1);
            a3 += __shfl_xor_sync(0xffffffffu, a3, 1);
            a4 += __shfl_xor_sync(0xffffffffu, a4, 1);
            a5 += __shfl_xor_sync(0xffffffffu, a5, 1);
            if (n2 < N_NODES && hf == 0) {
                float* o = g_agg6 + (size_t)n2 * F_IN;
                o[0] = a0; o[1] = a1; o[2] = a2;
                o[3] = a3; o[4] = a4; o[5] = a5;
            }
        }
    }
}

// ---- kernel 2: z0 = relu(agg6 @ W_in + b_in) . u_1 ; acc = c_10 ------------
__global__ __launch_bounds__(128) void z0_k(const float* __restrict__ W_in,
                                            const float* __restrict__ b_in) {
    int g = blockIdx.x * 128 + threadIdx.x;
    int n = g >> 1, half = g & 1;
    bool act = (n < N_NODES);
    float z = 0.f;
    if (act) {
        const float* a = g_agg6 + (size_t)n * F_IN;
        float a0 = a[0], a1 = a[1], a2 = a[2], a3 = a[3], a4 = a[4], a5 = a[5];
        const float4* W0 = (const float4*)W_in;     // [f][c]: f*128 + j
        const float4* B4 = (const float4*)b_in;
        const float4* U4 = (const float4*)g_uc[1];
        int j0 = half * 64;
        #pragma unroll 4
        for (int j = j0; j < j0 + 64; j++) {
            float4 w0 = W0[j],       w1 = W0[128 + j], w2 = W0[256 + j];
            float4 w3 = W0[384 + j], w4 = W0[512 + j], w5 = W0[640 + j];
            float4 bb = B4[j], uu = U4[j];
            float h;
            h = bb.x + a0*w0.x + a1*w1.x + a2*w2.x + a3*w3.x + a4*w4.x + a5*w5.x;
            z += fmaxf(h, 0.f) * uu.x;
            h = bb.y + a0*w0.y + a1*w1.y + a2*w2.y + a3*w3.y + a4*w4.y + a5*w5.y;
            z += fmaxf(h, 0.f) * uu.y;
            h = bb.z + a0*w0.z + a1*w1.z + a2*w2.z + a3*w3.z + a4*w4.z + a5*w5.z;
            z += fmaxf(h, 0.f) * uu.z;
            h = bb.w + a0*w0.w + a1*w1.w + a2*w2.w + a3*w3.w + a4*w4.w + a5*w5.w;
            z += fmaxf(h, 0.f) * uu.w;
        }
    }
    z += __shfl_xor_sync(0xffffffffu, z, 1);
    if (act && half == 0) {
        g_zd[0][n] = make_float2(z, 1.0f);
        g_acc[n] = g_c[10];                        // c_10 * d_0
    }
}

// ---- kernel 3 (x10): one aggregation pass, 8 threads per node --------------
__global__ __launch_bounds__(256) void pass_k(int p, const float* __restrict__ b_out,
                                              float* __restrict__ out) {
    int g = blockIdx.x * 256 + threadIdx.x;
    if (p == DEPTH && g == 0) { g_ctrA = 0; g_ctrB = 0; }  // self-clean barriers
    int n = g >> 3, sub = g & 7;
    bool act = (n < N_NODES);
    float sz = 0.f, sd = 0.f;
    if (act) {
        const float2* srcb = g_zd[(p - 1) & 1];
        int b = g_rowptr[n], e = g_rowptr[n + 1];
        for (int i = b + sub; i < e; i += 8) {
            float2 v = srcb[g_csr[i]];
            sz += v.x; sd += v.y;
        }
    }
    sz += __shfl_xor_sync(0xffffffffu, sz, 1);
    sd += __shfl_xor_sync(0xffffffffu, sd, 1);
    sz += __shfl_xor_sync(0xffffffffu, sz, 2);
    sd += __shfl_xor_sync(0xffffffffu, sd, 2);
    sz += __shfl_xor_sync(0xffffffffu, sz, 4);
    sd += __shfl_xor_sync(0xffffffffu, sd, 4);
    if (act && sub == 0) {
        if (p < DEPTH) {
            g_zd[p & 1][n] = make_float2(sz, sd);
            g_acc[n] += g_c[10 - p] * sd;
        } else {
            out[n] = sz + g_acc[n] + b_out[0];
        }
    }
}

// ---------------- launch ----------------------------------------------------
extern "C" void kernel_launch(void* const* d_in, const int* in_sizes, int n_in,
                              void* d_out, int out_size) {
    const float* features = (const float*)d_in[0];
    const float* W_in     = (const float*)d_in[1];
    const float* b_in     = (const float*)d_in[2];
    const float* Ws       = (const float*)d_in[3];
    const float* bs       = (const float*)d_in[4];
    const float* W_out    = (const float*)d_in[5];
    const float* b_out    = (const float*)d_in[6];
    const int*   src      = (const int*)d_in[7];
    const int*   dst      = (const int*)d_in[8];
    float* out = (float*)d_out;

    build_k<<<NB_BUILD, 256>>>(features, Ws, bs, W_out, src, dst);
    z0_k<<<157, 128>>>(W_in, b_in);
    for (int p = 1; p <= DEPTH; p++)
        pass_k<<<NB_PASS, 256>>>(p, b_out, out);
}